// round 11
// baseline (speedup 1.0000x reference)
#include <cuda_runtime.h>
#include <cuda_bf16.h>
#include <cstdint>

#define NTOK 8192
#define DIN  256
#define DOUT 256
#define NE   16
#define NH   512
#define SLOTS 18560   // >= 16384 + 16*127 padded routed slots

// ---------------------------------------------------------------------------
// Device scratch
// ---------------------------------------------------------------------------
__device__ int   g_cnt[NE];
__device__ int   g_rtok[NE * NTOK];
__device__ float g_rgate[NE * NTOK];

__device__ __nv_bfloat16 g_xhi[NTOK * DIN],  g_xlo[NTOK * DIN];
__device__ __nv_bfloat16 g_w1Thi[NE * NH * DIN],  g_w1Tlo[NE * NH * DIN];    // [e][n=512][k=256]
__device__ __nv_bfloat16 g_w2Thi[NE * NH * NH],   g_w2Tlo[NE * NH * NH];     // [e][512][512]
__device__ __nv_bfloat16 g_w3Thi[NE * DOUT * NH], g_w3Tlo[NE * DOUT * NH];   // [e][256][512]
__device__ __nv_bfloat16 g_h1hi[(size_t)SLOTS * NH], g_h1lo[(size_t)SLOTS * NH];
__device__ __nv_bfloat16 g_h2hi[(size_t)SLOTS * NH], g_h2lo[(size_t)SLOTS * NH];

// ---------------------------------------------------------------------------
// PTX helpers (compute_103-safe: cp.async + ldmatrix + mma.sync only)
// ---------------------------------------------------------------------------
__device__ __forceinline__ uint32_t smem_u32(const void* p) {
    uint32_t a;
    asm("{ .reg .u64 t; cvta.to.shared.u64 t, %1; cvt.u32.u64 %0, t; }" : "=r"(a) : "l"(p));
    return a;
}
#define CP16(dst, src) \
    asm volatile("cp.async.cg.shared.global [%0], [%1], 16;" :: "r"(dst), "l"(src) : "memory")
#define CP_COMMIT() asm volatile("cp.async.commit_group;" ::: "memory")
#define CP_WAIT(n)  asm volatile("cp.async.wait_group %0;" :: "n"(n) : "memory")

#define LDSM4(r, addr) \
    asm volatile("ldmatrix.sync.aligned.m8n8.x4.shared.b16 {%0,%1,%2,%3}, [%4];" \
        : "=r"((r)[0]), "=r"((r)[1]), "=r"((r)[2]), "=r"((r)[3]) : "r"(addr))

#define MMA16816(c, a, b) \
    asm volatile("mma.sync.aligned.m16n8k16.row.col.f32.bf16.bf16.f32 " \
        "{%0,%1,%2,%3}, {%4,%5,%6,%7}, {%8,%9}, {%0,%1,%2,%3};" \
        : "+f"((c)[0]), "+f"((c)[1]), "+f"((c)[2]), "+f"((c)[3]) \
        : "r"((a)[0]), "r"((a)[1]), "r"((a)[2]), "r"((a)[3]), "r"((b)[0]), "r"((b)[1]))

// Packed fp32x2 helpers (gate path)
#define FMA2(d, a, b) asm("fma.rn.f32x2 %0, %1, %2, %0;" : "+l"(d) : "l"(a), "l"(b))
#define DUP2(d, s)    asm("mov.b64 %0, {%1, %1};" : "=l"(d) : "f"(s))
#define UNPK(lo, hi, s) asm("mov.b64 {%0, %1}, %2;" : "=f"(lo), "=f"(hi) : "l"(s))

// Pair-packed 64B-row swizzle: logical (row, k32) stored in 128B phys rows.
// unit(row, u) = ((row&1)*4 + u) ^ ((row>>1)&7), u = k/8 in [0,4)
__device__ __forceinline__ uint32_t sw32(int row, int u) {
    return (uint32_t)((row >> 1) * 128 +
                      (((((row & 1) << 2) + u) ^ ((row >> 1) & 7)) << 4));
}

// ---------------------------------------------------------------------------
__global__ void zero_cnt_kernel() {
    if (threadIdx.x < NE) g_cnt[threadIdx.x] = 0;
}

// ---------------------------------------------------------------------------
// Fused prep: split_x + 3 weight transpose+splits, demuxed by blockIdx.x.
// ---------------------------------------------------------------------------
__global__ __launch_bounds__(256) void prep_kernel(
    const float* __restrict__ x,  const float* __restrict__ w1,
    const float* __restrict__ w2, const float* __restrict__ w3)
{
    const int bid = blockIdx.x;
    const int tid = threadIdx.x;

    if (bid < 4096) {
        int i = bid * 256 + tid;
        float2 v = ((const float2*)x)[i];
        __nv_bfloat16 h0 = __float2bfloat16(v.x), h1 = __float2bfloat16(v.y);
        float r0 = v.x - __bfloat162float(h0), r1 = v.y - __bfloat162float(h1);
        __nv_bfloat16 l0 = __float2bfloat16(r0), l1 = __float2bfloat16(r1);
        ((uint32_t*)g_xhi)[i] = (uint32_t)__bfloat16_as_ushort(h0) | ((uint32_t)__bfloat16_as_ushort(h1) << 16);
        ((uint32_t*)g_xlo)[i] = (uint32_t)__bfloat16_as_ushort(l0) | ((uint32_t)__bfloat16_as_ushort(l1) << 16);
        return;
    }

    __shared__ float t[32][33];
    const int tx = tid & 31, ty = tid >> 5;

    const float* src; long rs; int K, N, e, n0, k0;
    __nv_bfloat16 *dh, *dl;
    if (bid < 6144) {                    // w1
        int l = bid - 4096;
        e = l >> 7; int r = l & 127;
        n0 = (r & 15) * 32; k0 = (r >> 4) * 32;
        src = w1 + e * NH; rs = (long)NE * NH; K = DIN; N = NH;
        dh = g_w1Thi; dl = g_w1Tlo;
    } else if (bid < 10240) {            // w2
        int l = bid - 6144;
        e = l >> 8; int r = l & 255;
        n0 = (r & 15) * 32; k0 = (r >> 4) * 32;
        src = w2 + e * NH; rs = (long)NE * NH; K = NH; N = NH;
        dh = g_w2Thi; dl = g_w2Tlo;
    } else {                             // w3
        int l = bid - 10240;
        e = l >> 7; int r = l & 127;
        n0 = (r & 7) * 32; k0 = (r >> 3) * 32;
        src = w3 + e * DOUT; rs = (long)NE * DOUT; K = NH; N = DOUT;
        dh = g_w3Thi; dl = g_w3Tlo;
    }
    dh += (size_t)e * N * K;
    dl += (size_t)e * N * K;

#pragma unroll
    for (int i = 0; i < 4; ++i)
        t[ty + 8 * i][tx] = src[(long)(k0 + ty + 8 * i) * rs + n0 + tx];
    __syncthreads();
#pragma unroll
    for (int i = 0; i < 4; ++i) {
        float v = t[tx][ty + 8 * i];
        __nv_bfloat16 h = __float2bfloat16(v);
        float r = v - __bfloat162float(h);
        size_t idx = (size_t)(n0 + ty + 8 * i) * K + k0 + tx;
        dh[idx] = h;
        dl[idx] = __float2bfloat16(r);
    }
}

// ---------------------------------------------------------------------------
// Fused gate kernel (fp32-exact routing) — unchanged
// ---------------------------------------------------------------------------
template<int KDIM>
__device__ __forceinline__ void gemm_coreT(
    const float* __restrict__ St, const float* __restrict__ W, long ws,
    int c0, int c1, unsigned long long* accA, unsigned long long* accB)
{
#pragma unroll 2
    for (int k = 0; k < KDIM; k += 4) {
        const float* wp = W + (long)k * ws;
        unsigned long long ua[4], ub[4];
#pragma unroll
        for (int j = 0; j < 4; ++j) {
            float wa = wp[(long)j * ws + c0];
            float wb = wp[(long)j * ws + c1];
            DUP2(ua[j], wa); DUP2(ub[j], wb);
        }
#pragma unroll
        for (int j = 0; j < 4; ++j) {
            const ulonglong2* xp = (const ulonglong2*)(St + (k + j) * 32);
#pragma unroll
            for (int p = 0; p < 8; ++p) {
                ulonglong2 X = xp[p];
                FMA2(accA[2 * p],     X.x, ua[j]);
                FMA2(accA[2 * p + 1], X.y, ua[j]);
                FMA2(accB[2 * p],     X.x, ub[j]);
                FMA2(accB[2 * p + 1], X.y, ub[j]);
            }
        }
    }
}

#define HPAD 513
#define GPAD 20

__global__ __launch_bounds__(256) void gate_fused_kernel(
    const float* __restrict__ x,  const float* __restrict__ gw,
    const float* __restrict__ gb, const float* __restrict__ gow,
    const float* __restrict__ gob)
{
    extern __shared__ __align__(16) float dynsm[];
    float* Xs  = dynsm;                        // [256][32] transposed x tile
    float* hS  = dynsm + 8192;                 // [32][HPAD]
    float* gwS = dynsm + 8192 + 32 * HPAD;     // [512][GPAD]

    const int tid = threadIdx.x;
    const int wid = tid >> 5, lane = tid & 31;
    const int t0 = blockIdx.x * 32;

    {
        const int fb = wid * 32;
        float v[32];
#pragma unroll
        for (int r = 0; r < 32; ++r)
            v[r] = x[(long)(t0 + r) * DIN + fb + lane];
#pragma unroll
        for (int rr = 0; rr < 32; ++rr) {
            int r = (rr + lane) & 31;
            Xs[(fb + lane) * 32 + r] = v[r];
        }
    }
    __syncthreads();

    const int c0 = tid, c1 = tid + 256;
    unsigned long long accA[16], accB[16];
    float bb0 = gb[c0], bb1 = gb[c1];
#pragma unroll
    for (int p = 0; p < 16; ++p) { DUP2(accA[p], bb0); DUP2(accB[p], bb1); }
    gemm_coreT<DIN>(Xs, gw, NH, c0, c1, accA, accB);

#pragma unroll
    for (int p = 0; p < 16; ++p) {
        float lo, hi;
        UNPK(lo, hi, accA[p]);
        hS[(2 * p) * HPAD + c0]     = fmaxf(lo, 0.f);
        hS[(2 * p + 1) * HPAD + c0] = fmaxf(hi, 0.f);
        UNPK(lo, hi, accB[p]);
        hS[(2 * p) * HPAD + c1]     = fmaxf(lo, 0.f);
        hS[(2 * p + 1) * HPAD + c1] = fmaxf(hi, 0.f);
    }
    for (int idx = tid; idx < NH * NE; idx += 256) {
        int r = idx >> 4, c = idx & 15;
        gwS[r * GPAD + c] = gow[idx];
    }
    __syncthreads();

    const int t = tid >> 3, s = tid & 7;
    float l[NE];
#pragma unroll
    for (int e = 0; e < NE; ++e) l[e] = 0.f;
#pragma unroll 4
    for (int i = 0; i < 64; ++i) {
        int hidx = s + 8 * i;
        float v = hS[t * HPAD + hidx];
        const float4* gp = (const float4*)(gwS + hidx * GPAD);
        float4 a = gp[0], b = gp[1], c4 = gp[2], d = gp[3];
        l[0]  = fmaf(v, a.x,  l[0]);   l[1]  = fmaf(v, a.y,  l[1]);
        l[2]  = fmaf(v, a.z,  l[2]);   l[3]  = fmaf(v, a.w,  l[3]);
        l[4]  = fmaf(v, b.x,  l[4]);   l[5]  = fmaf(v, b.y,  l[5]);
        l[6]  = fmaf(v, b.z,  l[6]);   l[7]  = fmaf(v, b.w,  l[7]);
        l[8]  = fmaf(v, c4.x, l[8]);   l[9]  = fmaf(v, c4.y, l[9]);
        l[10] = fmaf(v, c4.z, l[10]);  l[11] = fmaf(v, c4.w, l[11]);
        l[12] = fmaf(v, d.x,  l[12]);  l[13] = fmaf(v, d.y,  l[13]);
        l[14] = fmaf(v, d.z,  l[14]);  l[15] = fmaf(v, d.w,  l[15]);
    }
#pragma unroll
    for (int m = 1; m < 8; m <<= 1)
#pragma unroll
        for (int e = 0; e < NE; ++e)
            l[e] += __shfl_xor_sync(0xffffffffu, l[e], m);

    if (s == 0) {
        float v0 = -1e30f, v1 = -1e30f;
        int i0 = 0, i1 = 0;
#pragma unroll
        for (int e = 0; e < NE; ++e) {
            float lg = l[e] + __ldg(gob + e);
            if (lg > v0)      { v1 = v0; i1 = i0; v0 = lg; i0 = e; }
            else if (lg > v1) { v1 = lg; i1 = e; }
        }
        float e1 = __expf(v1 - v0);
        float sden = 1.f + e1;
        float ga = 1.f / sden;
        float gb2 = e1 / sden;

        const int tok = t0 + t;
        int p0 = atomicAdd(&g_cnt[i0], 1);
        g_rtok[i0 * NTOK + p0]  = tok;
        g_rgate[i0 * NTOK + p0] = ga;
        int p1 = atomicAdd(&g_cnt[i1], 1);
        g_rtok[i1 * NTOK + p1]  = tok;
        g_rgate[i1 * NTOK + p1] = gb2;
    }
}

// ---------------------------------------------------------------------------
// HMMA split-bf16 GEMM, 4-stage cp.async pipeline, K-chunk 32.
// CTA: 128 M-slots x 256 N-cols; 512 threads, 16 warps = 4(M) x 4(N).
// Stage (48KB): Ahi 8K | Alo 8K | Bhi 16K | Blo 16K; 4 stages = 192KB.
// Pair-packed 64B-row swizzle (sw32). One __syncthreads per chunk;
// issue depth 3; empty commit groups keep the CP_WAIT(2) invariant.
// ---------------------------------------------------------------------------
#define STG_BYTES 49152

template<int MODE, int KF, int NW>
__global__ __launch_bounds__(512, 1) void mma_kernel(
    const float* __restrict__ bias, float* __restrict__ outp)
{
    const int e    = blockIdx.y;
    const int tile = blockIdx.x;
    const int cnt  = g_cnt[e];
    if (tile * 128 >= cnt) return;
    const int nbase = blockIdx.z * 256;
    const int m = min(128, cnt - tile * 128);

    int off = 0;
#pragma unroll
    for (int i = 0; i < NE; ++i)
        if (i < e) off += ((g_cnt[i] + 127) >> 7) << 7;
    const int slotbase = off + tile * 128;

    const __nv_bfloat16* Ahip = (MODE == 1) ? g_xhi : (MODE == 2) ? g_h1hi : g_h2hi;
    const __nv_bfloat16* Alop = (MODE == 1) ? g_xlo : (MODE == 2) ? g_h1lo : g_h2lo;
    const __nv_bfloat16* Bhi_e = ((MODE == 1) ? g_w1Thi : (MODE == 2) ? g_w2Thi : g_w3Thi)
                                 + (size_t)e * NW * KF;
    const __nv_bfloat16* Blo_e = ((MODE == 1) ? g_w1Tlo : (MODE == 2) ? g_w2Tlo : g_w3Tlo)
                                 + (size_t)e * NW * KF;
    __nv_bfloat16* Ohi = (MODE == 1) ? g_h1hi : g_h2hi;
    __nv_bfloat16* Olo = (MODE == 1) ? g_h1lo : g_h2lo;

    extern __shared__ char smp[];
    const uint32_t smb = smem_u32(smp);
    __shared__ int   toks[128];
    __shared__ float gts[128];
    __shared__ float sbias[256];

    const int tid  = threadIdx.x;
    const int wid  = tid >> 5, lane = tid & 31;
    const int wm   = wid & 3,  wn   = wid >> 2;   // 4 x 4 warp grid

    if (tid < 128 && MODE != 2) {
        int i = tile * 128 + tid;
        bool v = (i < cnt);
        toks[tid] = v ? g_rtok[e * NTOK + i] : 0;
        gts[tid]  = v ? g_rgate[e * NTOK + i] : 0.f;
    }
    if (tid < 256) sbias[tid] = bias[e * NW + nbase + tid];
    __syncthreads();

    const int NCH = KF / 32;

    // ---- async chunk loader: 6 cp.async of 16B per thread ----
    auto load_chunk = [&](int ch) {
        const int kbase = ch * 32;
        const uint32_t sb = smb + (ch & 3) * STG_BYTES;
        {   // A hi/lo: 512 16B-chunks each
            int row = tid >> 2, u = tid & 3;
            uint32_t d = sb + sw32(row, u);
            long arow = (MODE == 1) ? (long)toks[row] : (long)(slotbase + row);
            CP16(d,        Ahip + arow * KF + kbase + u * 8);
            CP16(d + 8192, Alop + arow * KF + kbase + u * 8);
        }
#pragma unroll
        for (int i = 0; i < 2; ++i) {   // B hi/lo: 1024 16B-chunks each
            int idx = tid + i * 512;
            int row = idx >> 2, u = idx & 3;
            uint32_t d = sb + 16384 + sw32(row, u);
            CP16(d,         Bhi_e + (size_t)(nbase + row) * KF + kbase + u * 8);
            CP16(d + 16384, Blo_e + (size_t)(nbase + row) * KF + kbase + u * 8);
        }
        CP_COMMIT();
    };

    float acc[2][8][4];
#pragma unroll
    for (int mf = 0; mf < 2; ++mf)
#pragma unroll
        for (int nf = 0; nf < 8; ++nf)
#pragma unroll
            for (int j = 0; j < 4; ++j) acc[mf][nf][j] = 0.f;

    load_chunk(0);
    load_chunk(1);
    load_chunk(2);

    for (int ch = 0; ch < NCH; ++ch) {
        CP_WAIT(2);          // chunk ch landed
        __syncthreads();     // all warps done with chunk ch-1 reads; data visible
        if (ch + 3 < NCH) load_chunk(ch + 3);
        else              CP_COMMIT();          // empty group keeps invariant

        const uint32_t sb  = smb + (ch & 3) * STG_BYTES;
        const uint32_t aHI = sb, aLO = sb + 8192, bHI = sb + 16384, bLO = sb + 32768;

#pragma unroll
        for (int ks = 0; ks < 2; ++ks) {
            const int k0 = ks * 16;
            // A fragments (row-major 16x16 via ldmatrix.x4)
            uint32_t ahi[2][4], alo[2][4];
            {
                int r_ = (lane & 7) + ((lane >> 3) & 1) * 8;
                int au = (k0 >> 3) + (lane >> 4);          // k-unit 0..3
#pragma unroll
                for (int mf = 0; mf < 2; ++mf) {
                    int r = wm * 32 + mf * 16 + r_;
                    uint32_t off2 = sw32(r, au);
                    LDSM4(ahi[mf], aHI + off2);
                    LDSM4(alo[mf], aLO + off2);
                }
            }
            // B fragments in two groups of 2 x 16-wide tiles
#pragma unroll
            for (int g = 0; g < 2; ++g) {
                uint32_t bhi[4][2], blo[4][2];
                int n_ = (lane & 7) + (lane >> 4) * 8;
                int bu = (k0 >> 3) + ((lane >> 3) & 1);    // k-unit 0..3
#pragma unroll
                for (int nb = 0; nb < 2; ++nb) {
                    int n = wn * 64 + (g * 2 + nb) * 16 + n_;
                    uint32_t off2 = sw32(n, bu);
                    uint32_t r4[4];
                    LDSM4(r4, bHI + off2);
                    bhi[2 * nb][0] = r4[0]; bhi[2 * nb][1] = r4[1];
                    bhi[2 * nb + 1][0] = r4[2]; bhi[2 * nb + 1][1] = r4[3];
                    LDSM4(r4, bLO + off2);
                    blo[2 * nb][0] = r4[0]; blo[2 * nb][1] = r4[1];
                    blo[2 * nb + 1][0] = r4[2]; blo[2 * nb + 1][1] = r4[3];
                }
#pragma unroll
                for (int mf = 0; mf < 2; ++mf)
#pragma unroll
                    for (int nf = 0; nf < 4; ++nf)
                        MMA16816(acc[mf][g * 4 + nf], ahi[mf], bhi[nf]);
#pragma unroll
                for (int mf = 0; mf < 2; ++mf)
#pragma unroll
                    for (int nf = 0; nf < 4; ++nf)
                        MMA16816(acc[mf][g * 4 + nf], alo[mf], bhi[nf]);
#pragma unroll
                for (int mf = 0; mf < 2; ++mf)
#pragma unroll
                    for (int nf = 0; nf < 4; ++nf)
                        MMA16816(acc[mf][g * 4 + nf], ahi[mf], blo[nf]);
            }
        }
    }

    // ---- epilogue ----
    const int grp = lane >> 2, t2 = (lane & 3) * 2;
#pragma unroll
    for (int mf = 0; mf < 2; ++mf) {
#pragma unroll
        for (int nf = 0; nf < 8; ++nf) {
            const float* c = acc[mf][nf];
            const int col = wn * 64 + nf * 8 + t2;        // 0..255 in-tile
#pragma unroll
            for (int half = 0; half < 2; ++half) {
                const int r = wm * 32 + mf * 16 + grp + half * 8;
                float v0 = c[half * 2 + 0] + sbias[col];
                float v1 = c[half * 2 + 1] + sbias[col + 1];
                if (MODE == 3) {
                    if (r < m) {
                        float g = gts[r];
                        float* orow = outp + (size_t)toks[r] * DOUT + nbase + col;
                        atomicAdd(orow,     g * v0);
                        atomicAdd(orow + 1, g * v1);
                    }
                } else {
                    v0 = fmaxf(v0, 0.f);
                    v1 = fmaxf(v1, 0.f);
                    __nv_bfloat16 h0 = __float2bfloat16(v0), h1 = __float2bfloat16(v1);
                    float r0 = v0 - __bfloat162float(h0), r1 = v1 - __bfloat162float(h1);
                    __nv_bfloat16 l0 = __float2bfloat16(r0), l1 = __float2bfloat16(r1);
                    size_t oi = (size_t)(slotbase + r) * NH + nbase + col;
                    *(uint32_t*)(Ohi + oi) =
                        (uint32_t)__bfloat16_as_ushort(h0) | ((uint32_t)__bfloat16_as_ushort(h1) << 16);
                    *(uint32_t*)(Olo + oi) =
                        (uint32_t)__bfloat16_as_ushort(l0) | ((uint32_t)__bfloat16_as_ushort(l1) << 16);
                }
            }
        }
    }
}

// ---------------------------------------------------------------------------
extern "C" void kernel_launch(void* const* d_in, const int* in_sizes, int n_in,
                              void* d_out, int out_size)
{
    const float* x   = (const float*)d_in[0];
    const float* gw  = (const float*)d_in[1];
    const float* gb  = (const float*)d_in[2];
    const float* gow = (const float*)d_in[3];
    const float* gob = (const float*)d_in[4];
    const float* w1  = (const float*)d_in[5];
    const float* b1  = (const float*)d_in[6];
    const float* w2  = (const float*)d_in[7];
    const float* b2  = (const float*)d_in[8];
    const float* w3  = (const float*)d_in[9];
    const float* b3  = (const float*)d_in[10];
    float* out = (float*)d_out;

    static cudaStream_t s_side = nullptr;
    static cudaEvent_t  s_evF = nullptr, s_evJ = nullptr;
    if (!s_side) {
        cudaStreamCreateWithFlags(&s_side, cudaStreamNonBlocking);
        cudaEventCreateWithFlags(&s_evF, cudaEventDisableTiming);
        cudaEventCreateWithFlags(&s_evJ, cudaEventDisableTiming);
    }

    const size_t smg = (size_t)(8192 + 32 * HPAD + NH * GPAD) * sizeof(float);  // ~136 KB
    const int    smm = 4 * STG_BYTES;                                           // 192 KB
    cudaFuncSetAttribute(gate_fused_kernel, cudaFuncAttributeMaxDynamicSharedMemorySize, (int)smg);
    cudaFuncSetAttribute(mma_kernel<1, DIN, NH>,  cudaFuncAttributeMaxDynamicSharedMemorySize, smm);
    cudaFuncSetAttribute(mma_kernel<2, NH, NH>,   cudaFuncAttributeMaxDynamicSharedMemorySize, smm);
    cudaFuncSetAttribute(mma_kernel<3, NH, DOUT>, cudaFuncAttributeMaxDynamicSharedMemorySize, smm);

    // ---- fork ----
    cudaEventRecord(s_evF, 0);
    cudaStreamWaitEvent(s_side, s_evF, 0);

    // main branch = gate path (launches #1, #2)
    zero_cnt_kernel<<<1, 32>>>();
    gate_fused_kernel<<<NTOK / 32, 256, smg>>>(x, gw, gb, gow, gob);

    // side branch = prep (launch #3) + memset
    cudaMemsetAsync(out, 0, (size_t)NTOK * DOUT * sizeof(float), s_side);
    prep_kernel<<<12288, 256, 0, s_side>>>(x, w1, w2, w3);

    // ---- join ----
    cudaEventRecord(s_evJ, s_side);
    cudaStreamWaitEvent(0, s_evJ, 0);

    // mma_kernel<1> is kernel launch #4 -> ncu (-s 5 -c 1) profiles it
    mma_kernel<1, DIN, NH><<<dim3(64, NE, 2), 512, smm>>>(b1, nullptr);
    mma_kernel<2, NH, NH><<<dim3(64, NE, 2), 512, smm>>>(b2, nullptr);
    mma_kernel<3, NH, DOUT><<<dim3(64, NE, 1), 512, smm>>>(b3, out);
}

// round 12
// speedup vs baseline: 1.5191x; 1.5191x over previous
#include <cuda_runtime.h>
#include <cuda_bf16.h>
#include <cuda_fp16.h>
#include <cstdint>

#define NTOK 8192
#define DIN  256
#define DOUT 256
#define NE   16
#define NH   512
#define SLOTS 18560   // >= 16384 + 16*127 padded routed slots

// ---------------------------------------------------------------------------
// Device scratch (expert path all single-plane fp16)
// ---------------------------------------------------------------------------
__device__ int   g_cnt[NE];
__device__ int   g_rtok[NE * NTOK];
__device__ float g_rgate[NE * NTOK];

__device__ __half g_xh[NTOK * DIN];
__device__ __half g_w1T[NE * NH * DIN];     // [e][n=512][k=256]
__device__ __half g_w2T[NE * NH * NH];      // [e][512][512]
__device__ __half g_w3T[NE * DOUT * NH];    // [e][256][512]
__device__ __half g_h1[(size_t)SLOTS * NH];
__device__ __half g_h2[(size_t)SLOTS * NH];

// ---------------------------------------------------------------------------
// PTX helpers (compute_103-safe: cp.async + ldmatrix + mma.sync only)
// ---------------------------------------------------------------------------
__device__ __forceinline__ uint32_t smem_u32(const void* p) {
    uint32_t a;
    asm("{ .reg .u64 t; cvta.to.shared.u64 t, %1; cvt.u32.u64 %0, t; }" : "=r"(a) : "l"(p));
    return a;
}
#define CP16(dst, src) \
    asm volatile("cp.async.cg.shared.global [%0], [%1], 16;" :: "r"(dst), "l"(src) : "memory")
#define CP_COMMIT() asm volatile("cp.async.commit_group;" ::: "memory")
#define CP_WAIT(n)  asm volatile("cp.async.wait_group %0;" :: "n"(n) : "memory")

#define LDSM4(r, addr) \
    asm volatile("ldmatrix.sync.aligned.m8n8.x4.shared.b16 {%0,%1,%2,%3}, [%4];" \
        : "=r"((r)[0]), "=r"((r)[1]), "=r"((r)[2]), "=r"((r)[3]) : "r"(addr))

#define MMA16816H(c, a, b) \
    asm volatile("mma.sync.aligned.m16n8k16.row.col.f32.f16.f16.f32 " \
        "{%0,%1,%2,%3}, {%4,%5,%6,%7}, {%8,%9}, {%0,%1,%2,%3};" \
        : "+f"((c)[0]), "+f"((c)[1]), "+f"((c)[2]), "+f"((c)[3]) \
        : "r"((a)[0]), "r"((a)[1]), "r"((a)[2]), "r"((a)[3]), "r"((b)[0]), "r"((b)[1]))

// Packed fp32x2 helpers (gate path)
#define FMA2(d, a, b) asm("fma.rn.f32x2 %0, %1, %2, %0;" : "+l"(d) : "l"(a), "l"(b))
#define DUP2(d, s)    asm("mov.b64 %0, {%1, %1};" : "=l"(d) : "f"(s))
#define UNPK(lo, hi, s) asm("mov.b64 {%0, %1}, %2;" : "=f"(lo), "=f"(hi) : "l"(s))

// Pair-packed 64B-row swizzle: logical (row, k-unit) in 128B phys rows.
__device__ __forceinline__ uint32_t sw32(int row, int u) {
    return (uint32_t)((row >> 1) * 128 +
                      (((((row & 1) << 2) + u) ^ ((row >> 1) & 7)) << 4));
}

// ---------------------------------------------------------------------------
__global__ void zero_cnt_kernel() {
    if (threadIdx.x < NE) g_cnt[threadIdx.x] = 0;
}

// ---------------------------------------------------------------------------
// Fused prep: x->fp16 + 3 weight transposes->fp16, demuxed by blockIdx.x.
//   [0, 2048)      : convert x (512 float2 pairs per block)
//   [2048, 4096)   : w1 [DIN,E,NH]  -> [e][NH][DIN]   (128 blk/e)
//   [4096, 8192)   : w2 [NH,E,NH]   -> [e][NH][NH]    (256 blk/e)
//   [8192, 10240)  : w3 [NH,E,DOUT] -> [e][DOUT][NH]  (128 blk/e)
// ---------------------------------------------------------------------------
__global__ __launch_bounds__(256) void prep_kernel(
    const float* __restrict__ x,  const float* __restrict__ w1,
    const float* __restrict__ w2, const float* __restrict__ w3)
{
    const int bid = blockIdx.x;
    const int tid = threadIdx.x;

    if (bid < 2048) {
        int base = bid * 512 + tid;
#pragma unroll
        for (int j = 0; j < 2; ++j) {
            int i = base + j * 256;
            float2 v = ((const float2*)x)[i];
            __half2 h = __floats2half2_rn(v.x, v.y);
            ((uint32_t*)g_xh)[i] = *(uint32_t*)&h;
        }
        return;
    }

    __shared__ float t[32][33];
    const int tx = tid & 31, ty = tid >> 5;

    const float* src; long rs; int K, N, e, n0, k0;
    __half* dh;
    if (bid < 4096) {                    // w1
        int l = bid - 2048;
        e = l >> 7; int r = l & 127;
        n0 = (r & 15) * 32; k0 = (r >> 4) * 32;
        src = w1 + e * NH; rs = (long)NE * NH; K = DIN; N = NH;
        dh = g_w1T;
    } else if (bid < 8192) {             // w2
        int l = bid - 4096;
        e = l >> 8; int r = l & 255;
        n0 = (r & 15) * 32; k0 = (r >> 4) * 32;
        src = w2 + e * NH; rs = (long)NE * NH; K = NH; N = NH;
        dh = g_w2T;
    } else {                             // w3
        int l = bid - 8192;
        e = l >> 7; int r = l & 127;
        n0 = (r & 7) * 32; k0 = (r >> 3) * 32;
        src = w3 + e * DOUT; rs = (long)NE * DOUT; K = NH; N = DOUT;
        dh = g_w3T;
    }
    dh += (size_t)e * N * K;

#pragma unroll
    for (int i = 0; i < 4; ++i)
        t[ty + 8 * i][tx] = src[(long)(k0 + ty + 8 * i) * rs + n0 + tx];
    __syncthreads();
#pragma unroll
    for (int i = 0; i < 4; ++i) {
        float v = t[tx][ty + 8 * i];
        dh[(size_t)(n0 + ty + 8 * i) * K + k0 + tx] = __float2half_rn(v);
    }
}

// ---------------------------------------------------------------------------
// Fused gate kernel (fp32-exact routing) — unchanged
// ---------------------------------------------------------------------------
template<int KDIM>
__device__ __forceinline__ void gemm_coreT(
    const float* __restrict__ St, const float* __restrict__ W, long ws,
    int c0, int c1, unsigned long long* accA, unsigned long long* accB)
{
#pragma unroll 2
    for (int k = 0; k < KDIM; k += 4) {
        const float* wp = W + (long)k * ws;
        unsigned long long ua[4], ub[4];
#pragma unroll
        for (int j = 0; j < 4; ++j) {
            float wa = wp[(long)j * ws + c0];
            float wb = wp[(long)j * ws + c1];
            DUP2(ua[j], wa); DUP2(ub[j], wb);
        }
#pragma unroll
        for (int j = 0; j < 4; ++j) {
            const ulonglong2* xp = (const ulonglong2*)(St + (k + j) * 32);
#pragma unroll
            for (int p = 0; p < 8; ++p) {
                ulonglong2 X = xp[p];
                FMA2(accA[2 * p],     X.x, ua[j]);
                FMA2(accA[2 * p + 1], X.y, ua[j]);
                FMA2(accB[2 * p],     X.x, ub[j]);
                FMA2(accB[2 * p + 1], X.y, ub[j]);
            }
        }
    }
}

#define HPAD 513
#define GPAD 20

__global__ __launch_bounds__(256) void gate_fused_kernel(
    const float* __restrict__ x,  const float* __restrict__ gw,
    const float* __restrict__ gb, const float* __restrict__ gow,
    const float* __restrict__ gob)
{
    extern __shared__ __align__(16) float dynsm[];
    float* Xs  = dynsm;                        // [256][32] transposed x tile
    float* hS  = dynsm + 8192;                 // [32][HPAD]
    float* gwS = dynsm + 8192 + 32 * HPAD;     // [512][GPAD]

    const int tid = threadIdx.x;
    const int wid = tid >> 5, lane = tid & 31;
    const int t0 = blockIdx.x * 32;

    {
        const int fb = wid * 32;
        float v[32];
#pragma unroll
        for (int r = 0; r < 32; ++r)
            v[r] = x[(long)(t0 + r) * DIN + fb + lane];
#pragma unroll
        for (int rr = 0; rr < 32; ++rr) {
            int r = (rr + lane) & 31;
            Xs[(fb + lane) * 32 + r] = v[r];
        }
    }
    __syncthreads();

    const int c0 = tid, c1 = tid + 256;
    unsigned long long accA[16], accB[16];
    float bb0 = gb[c0], bb1 = gb[c1];
#pragma unroll
    for (int p = 0; p < 16; ++p) { DUP2(accA[p], bb0); DUP2(accB[p], bb1); }
    gemm_coreT<DIN>(Xs, gw, NH, c0, c1, accA, accB);

#pragma unroll
    for (int p = 0; p < 16; ++p) {
        float lo, hi;
        UNPK(lo, hi, accA[p]);
        hS[(2 * p) * HPAD + c0]     = fmaxf(lo, 0.f);
        hS[(2 * p + 1) * HPAD + c0] = fmaxf(hi, 0.f);
        UNPK(lo, hi, accB[p]);
        hS[(2 * p) * HPAD + c1]     = fmaxf(lo, 0.f);
        hS[(2 * p + 1) * HPAD + c1] = fmaxf(hi, 0.f);
    }
    for (int idx = tid; idx < NH * NE; idx += 256) {
        int r = idx >> 4, c = idx & 15;
        gwS[r * GPAD + c] = gow[idx];
    }
    __syncthreads();

    const int t = tid >> 3, s = tid & 7;
    float l[NE];
#pragma unroll
    for (int e = 0; e < NE; ++e) l[e] = 0.f;
#pragma unroll 4
    for (int i = 0; i < 64; ++i) {
        int hidx = s + 8 * i;
        float v = hS[t * HPAD + hidx];
        const float4* gp = (const float4*)(gwS + hidx * GPAD);
        float4 a = gp[0], b = gp[1], c4 = gp[2], d = gp[3];
        l[0]  = fmaf(v, a.x,  l[0]);   l[1]  = fmaf(v, a.y,  l[1]);
        l[2]  = fmaf(v, a.z,  l[2]);   l[3]  = fmaf(v, a.w,  l[3]);
        l[4]  = fmaf(v, b.x,  l[4]);   l[5]  = fmaf(v, b.y,  l[5]);
        l[6]  = fmaf(v, b.z,  l[6]);   l[7]  = fmaf(v, b.w,  l[7]);
        l[8]  = fmaf(v, c4.x, l[8]);   l[9]  = fmaf(v, c4.y, l[9]);
        l[10] = fmaf(v, c4.z, l[10]);  l[11] = fmaf(v, c4.w, l[11]);
        l[12] = fmaf(v, d.x,  l[12]);  l[13] = fmaf(v, d.y,  l[13]);
        l[14] = fmaf(v, d.z,  l[14]);  l[15] = fmaf(v, d.w,  l[15]);
    }
#pragma unroll
    for (int m = 1; m < 8; m <<= 1)
#pragma unroll
        for (int e = 0; e < NE; ++e)
            l[e] += __shfl_xor_sync(0xffffffffu, l[e], m);

    if (s == 0) {
        float v0 = -1e30f, v1 = -1e30f;
        int i0 = 0, i1 = 0;
#pragma unroll
        for (int e = 0; e < NE; ++e) {
            float lg = l[e] + __ldg(gob + e);
            if (lg > v0)      { v1 = v0; i1 = i0; v0 = lg; i0 = e; }
            else if (lg > v1) { v1 = lg; i1 = e; }
        }
        float e1 = __expf(v1 - v0);
        float sden = 1.f + e1;
        float ga = 1.f / sden;
        float gb2 = e1 / sden;

        const int tok = t0 + t;
        int p0 = atomicAdd(&g_cnt[i0], 1);
        g_rtok[i0 * NTOK + p0]  = tok;
        g_rgate[i0 * NTOK + p0] = ga;
        int p1 = atomicAdd(&g_cnt[i1], 1);
        g_rtok[i1 * NTOK + p1]  = tok;
        g_rgate[i1 * NTOK + p1] = gb2;
    }
}

// ---------------------------------------------------------------------------
// HMMA fp16 single-product GEMM. MODE 1: X->H1, 2: H1->H2, 3: H2->out.
// CTA: 128 M x 256 N; 512 threads, 16 warps = 4(M) x 4(N); K-chunk 32,
// 4-stage cp.async pipeline. Stage (24KB): A 8K | B 16K.
// ---------------------------------------------------------------------------
#define STG_BYTES 24576

template<int MODE, int KF, int NW>
__global__ __launch_bounds__(512, 1) void mma_kernel(
    const float* __restrict__ bias, float* __restrict__ outp)
{
    const int e    = blockIdx.y;
    const int tile = blockIdx.x;
    const int cnt  = g_cnt[e];
    if (tile * 128 >= cnt) return;
    const int nbase = blockIdx.z * 256;
    const int m = min(128, cnt - tile * 128);

    int off = 0;
#pragma unroll
    for (int i = 0; i < NE; ++i)
        if (i < e) off += ((g_cnt[i] + 127) >> 7) << 7;
    const int slotbase = off + tile * 128;

    const __half* Ap  = (MODE == 1) ? g_xh : (MODE == 2) ? g_h1 : g_h2;
    const __half* B_e = ((MODE == 1) ? g_w1T : (MODE == 2) ? g_w2T : g_w3T)
                        + (size_t)e * NW * KF;
    __half* Op = (MODE == 1) ? g_h1 : g_h2;

    extern __shared__ char smp[];
    const uint32_t smb = smem_u32(smp);
    __shared__ int   toks[128];
    __shared__ float gts[128];
    __shared__ float sbias[256];

    const int tid  = threadIdx.x;
    const int wid  = tid >> 5, lane = tid & 31;
    const int wm   = wid & 3,  wn   = wid >> 2;   // 4 x 4 warp grid

    if (tid < 128 && MODE != 2) {
        int i = tile * 128 + tid;
        bool v = (i < cnt);
        toks[tid] = v ? g_rtok[e * NTOK + i] : 0;
        gts[tid]  = v ? g_rgate[e * NTOK + i] : 0.f;
    }
    if (tid < 256) sbias[tid] = bias[e * NW + nbase + tid];
    __syncthreads();

    const int NCH = KF / 32;

    // ---- async chunk loader: 3 cp.async of 16B per thread ----
    auto load_chunk = [&](int ch) {
        const int kbase = ch * 32;
        const uint32_t sb = smb + (ch & 3) * STG_BYTES;
        {   // A: 512 16B-chunks
            int row = tid >> 2, u = tid & 3;
            uint32_t d = sb + sw32(row, u);
            long arow = (MODE == 1) ? (long)toks[row] : (long)(slotbase + row);
            CP16(d, Ap + arow * KF + kbase + u * 8);
        }
#pragma unroll
        for (int i = 0; i < 2; ++i) {   // B: 1024 16B-chunks
            int idx = tid + i * 512;
            int row = idx >> 2, u = idx & 3;
            uint32_t d = sb + 8192 + sw32(row, u);
            CP16(d, B_e + (size_t)(nbase + row) * KF + kbase + u * 8);
        }
        CP_COMMIT();
    };

    float acc[2][8][4];
#pragma unroll
    for (int mf = 0; mf < 2; ++mf)
#pragma unroll
        for (int nf = 0; nf < 8; ++nf)
#pragma unroll
            for (int j = 0; j < 4; ++j) acc[mf][nf][j] = 0.f;

    load_chunk(0);
    load_chunk(1);
    load_chunk(2);

    for (int ch = 0; ch < NCH; ++ch) {
        CP_WAIT(2);
        __syncthreads();
        if (ch + 3 < NCH) load_chunk(ch + 3);
        else              CP_COMMIT();          // empty group keeps invariant

        const uint32_t sb = smb + (ch & 3) * STG_BYTES;
        const uint32_t aB = sb, bB = sb + 8192;

#pragma unroll
        for (int ks = 0; ks < 2; ++ks) {
            const int k0 = ks * 16;
            uint32_t af[2][4];
            {
                int r_ = (lane & 7) + ((lane >> 3) & 1) * 8;
                int au = (k0 >> 3) + (lane >> 4);
#pragma unroll
                for (int mf = 0; mf < 2; ++mf) {
                    int r = wm * 32 + mf * 16 + r_;
                    LDSM4(af[mf], aB + sw32(r, au));
                }
            }
#pragma unroll
            for (int g = 0; g < 2; ++g) {
                uint32_t bf[4][2];
                int n_ = (lane & 7) + (lane >> 4) * 8;
                int bu = (k0 >> 3) + ((lane >> 3) & 1);
#pragma unroll
                for (int nb = 0; nb < 2; ++nb) {
                    int n = wn * 64 + (g * 2 + nb) * 16 + n_;
                    uint32_t r4[4];
                    LDSM4(r4, bB + sw32(n, bu));
                    bf[2 * nb][0] = r4[0]; bf[2 * nb][1] = r4[1];
                    bf[2 * nb + 1][0] = r4[2]; bf[2 * nb + 1][1] = r4[3];
                }
#pragma unroll
                for (int mf = 0; mf < 2; ++mf)
#pragma unroll
                    for (int nf = 0; nf < 4; ++nf)
                        MMA16816H(acc[mf][g * 4 + nf], af[mf], bf[nf]);
            }
        }
    }

    // ---- epilogue ----
    const int grp = lane >> 2, t2 = (lane & 3) * 2;
#pragma unroll
    for (int mf = 0; mf < 2; ++mf) {
#pragma unroll
        for (int nf = 0; nf < 8; ++nf) {
            const float* c = acc[mf][nf];
            const int col = wn * 64 + nf * 8 + t2;        // 0..255 in-tile
#pragma unroll
            for (int half = 0; half < 2; ++half) {
                const int r = wm * 32 + mf * 16 + grp + half * 8;
                float v0 = c[half * 2 + 0] + sbias[col];
                float v1 = c[half * 2 + 1] + sbias[col + 1];
                if (MODE == 3) {
                    if (r < m) {
                        float g = gts[r];
                        float* orow = outp + (size_t)toks[r] * DOUT + nbase + col;
                        atomicAdd(orow,     g * v0);
                        atomicAdd(orow + 1, g * v1);
                    }
                } else {
                    __half2 h = __floats2half2_rn(fmaxf(v0, 0.f), fmaxf(v1, 0.f));
                    size_t oi = (size_t)(slotbase + r) * NH + nbase + col;
                    *(uint32_t*)(Op + oi) = *(uint32_t*)&h;
                }
            }
        }
    }
}

// ---------------------------------------------------------------------------
extern "C" void kernel_launch(void* const* d_in, const int* in_sizes, int n_in,
                              void* d_out, int out_size)
{
    const float* x   = (const float*)d_in[0];
    const float* gw  = (const float*)d_in[1];
    const float* gb  = (const float*)d_in[2];
    const float* gow = (const float*)d_in[3];
    const float* gob = (const float*)d_in[4];
    const float* w1  = (const float*)d_in[5];
    const float* b1  = (const float*)d_in[6];
    const float* w2  = (const float*)d_in[7];
    const float* b2  = (const float*)d_in[8];
    const float* w3  = (const float*)d_in[9];
    const float* b3  = (const float*)d_in[10];
    float* out = (float*)d_out;

    static cudaStream_t s_side = nullptr;
    static cudaEvent_t  s_evF = nullptr, s_evJ = nullptr;
    if (!s_side) {
        cudaStreamCreateWithFlags(&s_side, cudaStreamNonBlocking);
        cudaEventCreateWithFlags(&s_evF, cudaEventDisableTiming);
        cudaEventCreateWithFlags(&s_evJ, cudaEventDisableTiming);
    }

    const size_t smg = (size_t)(8192 + 32 * HPAD + NH * GPAD) * sizeof(float);  // ~136 KB
    const int    smm = 4 * STG_BYTES;                                           // 96 KB
    cudaFuncSetAttribute(gate_fused_kernel, cudaFuncAttributeMaxDynamicSharedMemorySize, (int)smg);
    cudaFuncSetAttribute(mma_kernel<1, DIN, NH>,  cudaFuncAttributeMaxDynamicSharedMemorySize, smm);
    cudaFuncSetAttribute(mma_kernel<2, NH, NH>,   cudaFuncAttributeMaxDynamicSharedMemorySize, smm);
    cudaFuncSetAttribute(mma_kernel<3, NH, DOUT>, cudaFuncAttributeMaxDynamicSharedMemorySize, smm);

    // ---- fork ----
    cudaEventRecord(s_evF, 0);
    cudaStreamWaitEvent(s_side, s_evF, 0);

    // main branch = gate path (launches #1, #2)
    zero_cnt_kernel<<<1, 32>>>();
    gate_fused_kernel<<<NTOK / 32, 256, smg>>>(x, gw, gb, gow, gob);

    // side branch = prep (launch #3) + memset
    cudaMemsetAsync(out, 0, (size_t)NTOK * DOUT * sizeof(float), s_side);
    prep_kernel<<<10240, 256, 0, s_side>>>(x, w1, w2, w3);

    // ---- join ----
    cudaEventRecord(s_evJ, s_side);
    cudaStreamWaitEvent(0, s_evJ, 0);

    // mma_kernel<1> is kernel launch #4 -> ncu (-s 5 -c 1) profiles it
    mma_kernel<1, DIN, NH><<<dim3(64, NE, 2), 512, smm>>>(b1, nullptr);
    mma_kernel<2, NH, NH><<<dim3(64, NE, 2), 512, smm>>>(b2, nullptr);
    mma_kernel<3, NH, DOUT><<<dim3(64, NE, 1), 512, smm>>>(b3, out);
}

// round 13
// speedup vs baseline: 1.8053x; 1.1884x over previous
#include <cuda_runtime.h>
#include <cuda_bf16.h>
#include <cuda_fp16.h>
#include <cstdint>

#define NTOK 8192
#define DIN  256
#define DOUT 256
#define NE   16
#define NH   512
#define SLOTS 18560   // >= 16384 + 16*127 padded routed slots

// ---------------------------------------------------------------------------
// Device scratch
// ---------------------------------------------------------------------------
__device__ int   g_cnt[NE];
__device__ int   g_rtok[NE * NTOK];
__device__ float g_rgate[NE * NTOK];
__device__ float g_logits[NTOK * NE];

__device__ __half g_xh[NTOK * DIN], g_xlo[NTOK * DIN];
__device__ __half g_gwh[NH * DIN],  g_gwl[NH * DIN];    // gate_w planes [n=512][k=256]
__device__ __half g_w1T[NE * NH * DIN];     // [e][n=512][k=256]
__device__ __half g_w2T[NE * NH * NH];      // [e][512][512]
__device__ __half g_w3T[NE * DOUT * NH];    // [e][256][512]
__device__ __half g_h1[(size_t)SLOTS * NH];
__device__ __half g_h2[(size_t)SLOTS * NH];

// ---------------------------------------------------------------------------
// PTX helpers (compute_103-safe: cp.async + ldmatrix + mma.sync only)
// ---------------------------------------------------------------------------
__device__ __forceinline__ uint32_t smem_u32(const void* p) {
    uint32_t a;
    asm("{ .reg .u64 t; cvta.to.shared.u64 t, %1; cvt.u32.u64 %0, t; }" : "=r"(a) : "l"(p));
    return a;
}
#define CP16(dst, src) \
    asm volatile("cp.async.cg.shared.global [%0], [%1], 16;" :: "r"(dst), "l"(src) : "memory")
#define CP_COMMIT() asm volatile("cp.async.commit_group;" ::: "memory")
#define CP_WAIT(n)  asm volatile("cp.async.wait_group %0;" :: "n"(n) : "memory")

#define LDSM4(r, addr) \
    asm volatile("ldmatrix.sync.aligned.m8n8.x4.shared.b16 {%0,%1,%2,%3}, [%4];" \
        : "=r"((r)[0]), "=r"((r)[1]), "=r"((r)[2]), "=r"((r)[3]) : "r"(addr))

#define MMA16816H(c, a, b) \
    asm volatile("mma.sync.aligned.m16n8k16.row.col.f32.f16.f16.f32 " \
        "{%0,%1,%2,%3}, {%4,%5,%6,%7}, {%8,%9}, {%0,%1,%2,%3};" \
        : "+f"((c)[0]), "+f"((c)[1]), "+f"((c)[2]), "+f"((c)[3]) \
        : "r"((a)[0]), "r"((a)[1]), "r"((a)[2]), "r"((a)[3]), "r"((b)[0]), "r"((b)[1]))

// Pair-packed 64B-row swizzle: logical (row, k-unit) in 128B phys rows.
__device__ __forceinline__ uint32_t sw32(int row, int u) {
    return (uint32_t)((row >> 1) * 128 +
                      (((((row & 1) << 2) + u) ^ ((row >> 1) & 7)) << 4));
}

__device__ __forceinline__ __half2 split_hi_lo(float v, __half& lo) {
    __half h = __float2half_rn(v);
    lo = __float2half_rn(v - __half2float(h));
    return __half2();  // unused
}

// ---------------------------------------------------------------------------
__global__ void zero_cnt_kernel() {
    if (threadIdx.x < NE) g_cnt[threadIdx.x] = 0;
}

// ---------------------------------------------------------------------------
// prep_gate: x -> hi/lo fp16 planes; gate_w -> transposed hi/lo planes;
// g_logits <- broadcast gate_out_b.
//   [0, 2048)      : x split (512 float2 pairs per block)
//   [2048, 2176)   : gw [256k][512n] -> [512n][256k] hi/lo (128 tiles)
//   [2176, 2688)   : g_logits init
// ---------------------------------------------------------------------------
__global__ __launch_bounds__(256) void prep_gate_kernel(
    const float* __restrict__ x, const float* __restrict__ gw,
    const float* __restrict__ gob)
{
    const int bid = blockIdx.x;
    const int tid = threadIdx.x;

    if (bid < 2048) {
        int base = bid * 512 + tid;
#pragma unroll
        for (int j = 0; j < 2; ++j) {
            int i = base + j * 256;
            float2 v = ((const float2*)x)[i];
            __half h0 = __float2half_rn(v.x), h1 = __float2half_rn(v.y);
            __half l0 = __float2half_rn(v.x - __half2float(h0));
            __half l1 = __float2half_rn(v.y - __half2float(h1));
            __half2 hh = __halves2half2(h0, h1), ll = __halves2half2(l0, l1);
            ((uint32_t*)g_xh)[i]  = *(uint32_t*)&hh;
            ((uint32_t*)g_xlo)[i] = *(uint32_t*)&ll;
        }
        return;
    }
    if (bid < 2176) {
        __shared__ float t[32][33];
        const int tx = tid & 31, ty = tid >> 5;
        int r = bid - 2048;
        int n0 = (r & 15) * 32, k0 = (r >> 4) * 32;
#pragma unroll
        for (int i = 0; i < 4; ++i)
            t[ty + 8 * i][tx] = gw[(long)(k0 + ty + 8 * i) * NH + n0 + tx];
        __syncthreads();
#pragma unroll
        for (int i = 0; i < 4; ++i) {
            float v = t[tx][ty + 8 * i];
            __half h = __float2half_rn(v);
            __half l = __float2half_rn(v - __half2float(h));
            size_t idx = (size_t)(n0 + ty + 8 * i) * DIN + k0 + tx;
            g_gwh[idx] = h;
            g_gwl[idx] = l;
        }
        return;
    }
    {
        int i = (bid - 2176) * 256 + tid;     // 512 blocks x 256 = 131072
        g_logits[i] = gob[i & 15];
    }
}

// ---------------------------------------------------------------------------
// prep_expert: 3 weight transposes -> single fp16 planes.
//   [0, 2048)    : w1 ; [2048, 6144) : w2 ; [6144, 8192) : w3
// ---------------------------------------------------------------------------
__global__ __launch_bounds__(256) void prep_expert_kernel(
    const float* __restrict__ w1, const float* __restrict__ w2,
    const float* __restrict__ w3)
{
    const int bid = blockIdx.x;
    const int tid = threadIdx.x;
    __shared__ float t[32][33];
    const int tx = tid & 31, ty = tid >> 5;

    const float* src; long rs; int K, N, e, n0, k0;
    __half* dh;
    if (bid < 2048) {                    // w1
        int l = bid;
        e = l >> 7; int r = l & 127;
        n0 = (r & 15) * 32; k0 = (r >> 4) * 32;
        src = w1 + e * NH; rs = (long)NE * NH; K = DIN; N = NH;
        dh = g_w1T;
    } else if (bid < 6144) {             // w2
        int l = bid - 2048;
        e = l >> 8; int r = l & 255;
        n0 = (r & 15) * 32; k0 = (r >> 4) * 32;
        src = w2 + e * NH; rs = (long)NE * NH; K = NH; N = NH;
        dh = g_w2T;
    } else {                             // w3
        int l = bid - 6144;
        e = l >> 7; int r = l & 127;
        n0 = (r & 7) * 32; k0 = (r >> 3) * 32;
        src = w3 + e * DOUT; rs = (long)NE * DOUT; K = NH; N = DOUT;
        dh = g_w3T;
    }
    dh += (size_t)e * N * K;

#pragma unroll
    for (int i = 0; i < 4; ++i)
        t[ty + 8 * i][tx] = src[(long)(k0 + ty + 8 * i) * rs + n0 + tx];
    __syncthreads();
#pragma unroll
    for (int i = 0; i < 4; ++i)
        dh[(size_t)(n0 + ty + 8 * i) * K + k0 + tx] = __float2half_rn(t[tx][ty + 8 * i]);
}

// ---------------------------------------------------------------------------
// gate_mma: 3-product split-fp16 hidden GEMM + in-CTA partial logits.
// Grid (64, 2): 128-token tile x 256-N half. K=256, 8 chunks of 32, 4-stage
// pipeline (stage 48KB: Ahi 8K | Alo 8K | Bhi 16K | Blo 16K; 192KB total).
// Epilogue: relu(h+gb) -> smem, 8-thr/token dot with gow half, shfl reduce,
// atomicAdd partial logits (2 commutative addends per (tok,e) -> deterministic).
// ---------------------------------------------------------------------------
#define GSTG 49152
#define HSP  264
#define GPAD 20

__global__ __launch_bounds__(512, 1) void gate_mma_kernel(
    const float* __restrict__ gb, const float* __restrict__ gow)
{
    const int tile  = blockIdx.x;
    const int nbase = blockIdx.y * 256;

    extern __shared__ char smp[];
    const uint32_t smb = smem_u32(smp);
    __shared__ float sbias[256];

    const int tid  = threadIdx.x;
    const int wid  = tid >> 5, lane = tid & 31;
    const int wm   = wid & 3,  wn   = wid >> 2;

    if (tid < 256) sbias[tid] = gb[nbase + tid];
    __syncthreads();

    auto load_chunk = [&](int ch) {
        const int kbase = ch * 32;
        const uint32_t sb = smb + (ch & 3) * GSTG;
        {
            int row = tid >> 2, u = tid & 3;
            uint32_t d = sb + sw32(row, u);
            long arow = (long)tile * 128 + row;
            CP16(d,        g_xh  + arow * DIN + kbase + u * 8);
            CP16(d + 8192, g_xlo + arow * DIN + kbase + u * 8);
        }
#pragma unroll
        for (int i = 0; i < 2; ++i) {
            int idx = tid + i * 512;
            int row = idx >> 2, u = idx & 3;
            uint32_t d = sb + 16384 + sw32(row, u);
            CP16(d,         g_gwh + (size_t)(nbase + row) * DIN + kbase + u * 8);
            CP16(d + 16384, g_gwl + (size_t)(nbase + row) * DIN + kbase + u * 8);
        }
        CP_COMMIT();
    };

    float acc[2][8][4];
#pragma unroll
    for (int mf = 0; mf < 2; ++mf)
#pragma unroll
        for (int nf = 0; nf < 8; ++nf)
#pragma unroll
            for (int j = 0; j < 4; ++j) acc[mf][nf][j] = 0.f;

    load_chunk(0);
    load_chunk(1);
    load_chunk(2);

    const int NCH = DIN / 32;
    for (int ch = 0; ch < NCH; ++ch) {
        CP_WAIT(2);
        __syncthreads();
        if (ch + 3 < NCH) load_chunk(ch + 3);
        else              CP_COMMIT();

        const uint32_t sb  = smb + (ch & 3) * GSTG;
        const uint32_t aHI = sb, aLO = sb + 8192, bHI = sb + 16384, bLO = sb + 32768;

#pragma unroll
        for (int ks = 0; ks < 2; ++ks) {
            const int k0 = ks * 16;
            uint32_t ahi[2][4], alo[2][4];
            {
                int r_ = (lane & 7) + ((lane >> 3) & 1) * 8;
                int au = (k0 >> 3) + (lane >> 4);
#pragma unroll
                for (int mf = 0; mf < 2; ++mf) {
                    int r = wm * 32 + mf * 16 + r_;
                    LDSM4(ahi[mf], aHI + sw32(r, au));
                    LDSM4(alo[mf], aLO + sw32(r, au));
                }
            }
#pragma unroll
            for (int g = 0; g < 2; ++g) {
                uint32_t bhi[4][2], blo[4][2];
                int n_ = (lane & 7) + (lane >> 4) * 8;
                int bu = (k0 >> 3) + ((lane >> 3) & 1);
#pragma unroll
                for (int nb = 0; nb < 2; ++nb) {
                    int n = wn * 64 + (g * 2 + nb) * 16 + n_;
                    uint32_t r4[4];
                    LDSM4(r4, bHI + sw32(n, bu));
                    bhi[2 * nb][0] = r4[0]; bhi[2 * nb][1] = r4[1];
                    bhi[2 * nb + 1][0] = r4[2]; bhi[2 * nb + 1][1] = r4[3];
                    LDSM4(r4, bLO + sw32(n, bu));
                    blo[2 * nb][0] = r4[0]; blo[2 * nb][1] = r4[1];
                    blo[2 * nb + 1][0] = r4[2]; blo[2 * nb + 1][1] = r4[3];
                }
#pragma unroll
                for (int mf = 0; mf < 2; ++mf)
#pragma unroll
                    for (int nf = 0; nf < 4; ++nf)
                        MMA16816H(acc[mf][g * 4 + nf], ahi[mf], bhi[nf]);
#pragma unroll
                for (int mf = 0; mf < 2; ++mf)
#pragma unroll
                    for (int nf = 0; nf < 4; ++nf)
                        MMA16816H(acc[mf][g * 4 + nf], alo[mf], bhi[nf]);
#pragma unroll
                for (int mf = 0; mf < 2; ++mf)
#pragma unroll
                    for (int nf = 0; nf < 4; ++nf)
                        MMA16816H(acc[mf][g * 4 + nf], ahi[mf], blo[nf]);
            }
        }
    }
    __syncthreads();   // mainloop stage reads done; smem is ours to reuse

    // ---- epilogue: partial logits ----
    float* Hsm  = (float*)smp;            // [64][HSP]
    float* gowS = Hsm + 64 * HSP;         // [256][GPAD]
    for (int idx = tid; idx < 256 * NE; idx += 512) {
        int r = idx >> 4, c = idx & 15;
        gowS[r * GPAD + c] = gow[(nbase + r) * NE + c];
    }

    const int grp = lane >> 2, t2 = (lane & 3) * 2;
#pragma unroll
    for (int hp = 0; hp < 2; ++hp) {      // token half-pass: rows hp*64..+64
        if (hp == 1) __syncthreads();     // half-0 logits reads done
        if ((wm >> 1) == hp) {
            int rbase = (wm & 1) * 32;
#pragma unroll
            for (int mf = 0; mf < 2; ++mf)
#pragma unroll
                for (int nf = 0; nf < 8; ++nf) {
                    const float* c = acc[mf][nf];
                    int col = wn * 64 + nf * 8 + t2;
#pragma unroll
                    for (int h8 = 0; h8 < 2; ++h8) {
                        int lr = rbase + mf * 16 + grp + h8 * 8;
                        Hsm[lr * HSP + col]     = fmaxf(c[h8 * 2] + sbias[col], 0.f);
                        Hsm[lr * HSP + col + 1] = fmaxf(c[h8 * 2 + 1] + sbias[col + 1], 0.f);
                    }
                }
        }
        __syncthreads();                  // Hsm (+ gowS on first pass) visible

        const int t = tid >> 3, s = tid & 7;
        float l[NE];
#pragma unroll
        for (int e = 0; e < NE; ++e) l[e] = 0.f;
#pragma unroll 4
        for (int i = 0; i < 32; ++i) {
            int rk = s + 8 * i;
            float v = Hsm[t * HSP + rk];
            const float4* gp = (const float4*)(gowS + rk * GPAD);
            float4 a = gp[0], b = gp[1], c4 = gp[2], d = gp[3];
            l[0]  = fmaf(v, a.x,  l[0]);   l[1]  = fmaf(v, a.y,  l[1]);
            l[2]  = fmaf(v, a.z,  l[2]);   l[3]  = fmaf(v, a.w,  l[3]);
            l[4]  = fmaf(v, b.x,  l[4]);   l[5]  = fmaf(v, b.y,  l[5]);
            l[6]  = fmaf(v, b.z,  l[6]);   l[7]  = fmaf(v, b.w,  l[7]);
            l[8]  = fmaf(v, c4.x, l[8]);   l[9]  = fmaf(v, c4.y, l[9]);
            l[10] = fmaf(v, c4.z, l[10]);  l[11] = fmaf(v, c4.w, l[11]);
            l[12] = fmaf(v, d.x,  l[12]);  l[13] = fmaf(v, d.y,  l[13]);
            l[14] = fmaf(v, d.z,  l[14]);  l[15] = fmaf(v, d.w,  l[15]);
        }
#pragma unroll
        for (int m2 = 1; m2 < 8; m2 <<= 1)
#pragma unroll
            for (int e = 0; e < NE; ++e)
                l[e] += __shfl_xor_sync(0xffffffffu, l[e], m2);

        int tok = tile * 128 + hp * 64 + t;
        atomicAdd(&g_logits[tok * NE + 2 * s],     l[2 * s]);
        atomicAdd(&g_logits[tok * NE + 2 * s + 1], l[2 * s + 1]);
    }
}

// ---------------------------------------------------------------------------
// route: top-2 + softmax + routing append, one thread per token.
// ---------------------------------------------------------------------------
__global__ __launch_bounds__(256) void route_kernel()
{
    const int tok = blockIdx.x * 256 + threadIdx.x;
    const float* L = g_logits + tok * NE;
    float v0 = -1e30f, v1 = -1e30f;
    int i0 = 0, i1 = 0;
#pragma unroll
    for (int e = 0; e < NE; ++e) {
        float lg = L[e];
        if (lg > v0)      { v1 = v0; i1 = i0; v0 = lg; i0 = e; }
        else if (lg > v1) { v1 = lg; i1 = e; }
    }
    float e1 = __expf(v1 - v0);
    float sden = 1.f + e1;
    int p0 = atomicAdd(&g_cnt[i0], 1);
    g_rtok[i0 * NTOK + p0]  = tok;
    g_rgate[i0 * NTOK + p0] = 1.f / sden;
    int p1 = atomicAdd(&g_cnt[i1], 1);
    g_rtok[i1 * NTOK + p1]  = tok;
    g_rgate[i1 * NTOK + p1] = e1 / sden;
}

// ---------------------------------------------------------------------------
// Expert HMMA fp16 single-product GEMM (unchanged from R12).
// ---------------------------------------------------------------------------
#define STG_BYTES 24576

template<int MODE, int KF, int NW>
__global__ __launch_bounds__(512, 1) void mma_kernel(
    const float* __restrict__ bias, float* __restrict__ outp)
{
    const int e    = blockIdx.y;
    const int tile = blockIdx.x;
    const int cnt  = g_cnt[e];
    if (tile * 128 >= cnt) return;
    const int nbase = blockIdx.z * 256;
    const int m = min(128, cnt - tile * 128);

    int off = 0;
#pragma unroll
    for (int i = 0; i < NE; ++i)
        if (i < e) off += ((g_cnt[i] + 127) >> 7) << 7;
    const int slotbase = off + tile * 128;

    const __half* Ap  = (MODE == 1) ? g_xh : (MODE == 2) ? g_h1 : g_h2;
    const __half* B_e = ((MODE == 1) ? g_w1T : (MODE == 2) ? g_w2T : g_w3T)
                        + (size_t)e * NW * KF;
    __half* Op = (MODE == 1) ? g_h1 : g_h2;

    extern __shared__ char smp[];
    const uint32_t smb = smem_u32(smp);
    __shared__ int   toks[128];
    __shared__ float gts[128];
    __shared__ float sbias[256];

    const int tid  = threadIdx.x;
    const int wid  = tid >> 5, lane = tid & 31;
    const int wm   = wid & 3,  wn   = wid >> 2;

    if (tid < 128 && MODE != 2) {
        int i = tile * 128 + tid;
        bool v = (i < cnt);
        toks[tid] = v ? g_rtok[e * NTOK + i] : 0;
        gts[tid]  = v ? g_rgate[e * NTOK + i] : 0.f;
    }
    if (tid < 256) sbias[tid] = bias[e * NW + nbase + tid];
    __syncthreads();

    const int NCH = KF / 32;

    auto load_chunk = [&](int ch) {
        const int kbase = ch * 32;
        const uint32_t sb = smb + (ch & 3) * STG_BYTES;
        {
            int row = tid >> 2, u = tid & 3;
            uint32_t d = sb + sw32(row, u);
            long arow = (MODE == 1) ? (long)toks[row] : (long)(slotbase + row);
            CP16(d, Ap + arow * KF + kbase + u * 8);
        }
#pragma unroll
        for (int i = 0; i < 2; ++i) {
            int idx = tid + i * 512;
            int row = idx >> 2, u = idx & 3;
            uint32_t d = sb + 8192 + sw32(row, u);
            CP16(d, B_e + (size_t)(nbase + row) * KF + kbase + u * 8);
        }
        CP_COMMIT();
    };

    float acc[2][8][4];
#pragma unroll
    for (int mf = 0; mf < 2; ++mf)
#pragma unroll
        for (int nf = 0; nf < 8; ++nf)
#pragma unroll
            for (int j = 0; j < 4; ++j) acc[mf][nf][j] = 0.f;

    load_chunk(0);
    load_chunk(1);
    load_chunk(2);

    for (int ch = 0; ch < NCH; ++ch) {
        CP_WAIT(2);
        __syncthreads();
        if (ch + 3 < NCH) load_chunk(ch + 3);
        else              CP_COMMIT();

        const uint32_t sb = smb + (ch & 3) * STG_BYTES;
        const uint32_t aB = sb, bB = sb + 8192;

#pragma unroll
        for (int ks = 0; ks < 2; ++ks) {
            const int k0 = ks * 16;
            uint32_t af[2][4];
            {
                int r_ = (lane & 7) + ((lane >> 3) & 1) * 8;
                int au = (k0 >> 3) + (lane >> 4);
#pragma unroll
                for (int mf = 0; mf < 2; ++mf) {
                    int r = wm * 32 + mf * 16 + r_;
                    LDSM4(af[mf], aB + sw32(r, au));
                }
            }
#pragma unroll
            for (int g = 0; g < 2; ++g) {
                uint32_t bf[4][2];
                int n_ = (lane & 7) + (lane >> 4) * 8;
                int bu = (k0 >> 3) + ((lane >> 3) & 1);
#pragma unroll
                for (int nb = 0; nb < 2; ++nb) {
                    int n = wn * 64 + (g * 2 + nb) * 16 + n_;
                    uint32_t r4[4];
                    LDSM4(r4, bB + sw32(n, bu));
                    bf[2 * nb][0] = r4[0]; bf[2 * nb][1] = r4[1];
                    bf[2 * nb + 1][0] = r4[2]; bf[2 * nb + 1][1] = r4[3];
                }
#pragma unroll
                for (int mf = 0; mf < 2; ++mf)
#pragma unroll
                    for (int nf = 0; nf < 4; ++nf)
                        MMA16816H(acc[mf][g * 4 + nf], af[mf], bf[nf]);
            }
        }
    }

    const int grp = lane >> 2, t2 = (lane & 3) * 2;
#pragma unroll
    for (int mf = 0; mf < 2; ++mf) {
#pragma unroll
        for (int nf = 0; nf < 8; ++nf) {
            const float* c = acc[mf][nf];
            const int col = wn * 64 + nf * 8 + t2;
#pragma unroll
            for (int half = 0; half < 2; ++half) {
                const int r = wm * 32 + mf * 16 + grp + half * 8;
                float v0 = c[half * 2 + 0] + sbias[col];
                float v1 = c[half * 2 + 1] + sbias[col + 1];
                if (MODE == 3) {
                    if (r < m) {
                        float g = gts[r];
                        float* orow = outp + (size_t)toks[r] * DOUT + nbase + col;
                        atomicAdd(orow,     g * v0);
                        atomicAdd(orow + 1, g * v1);
                    }
                } else {
                    __half2 h = __floats2half2_rn(fmaxf(v0, 0.f), fmaxf(v1, 0.f));
                    size_t oi = (size_t)(slotbase + r) * NH + nbase + col;
                    *(uint32_t*)(Op + oi) = *(uint32_t*)&h;
                }
            }
        }
    }
}

// ---------------------------------------------------------------------------
extern "C" void kernel_launch(void* const* d_in, const int* in_sizes, int n_in,
                              void* d_out, int out_size)
{
    const float* x   = (const float*)d_in[0];
    const float* gw  = (const float*)d_in[1];
    const float* gb  = (const float*)d_in[2];
    const float* gow = (const float*)d_in[3];
    const float* gob = (const float*)d_in[4];
    const float* w1  = (const float*)d_in[5];
    const float* b1  = (const float*)d_in[6];
    const float* w2  = (const float*)d_in[7];
    const float* b2  = (const float*)d_in[8];
    const float* w3  = (const float*)d_in[9];
    const float* b3  = (const float*)d_in[10];
    float* out = (float*)d_out;

    static cudaStream_t s_side = nullptr;
    static cudaEvent_t  s_evF = nullptr, s_evJ = nullptr;
    if (!s_side) {
        cudaStreamCreateWithFlags(&s_side, cudaStreamNonBlocking);
        cudaEventCreateWithFlags(&s_evF, cudaEventDisableTiming);
        cudaEventCreateWithFlags(&s_evJ, cudaEventDisableTiming);
    }

    const int smg = 4 * GSTG;        // 192 KB (also covers epilogue Hs+gowS)
    const int smm = 4 * STG_BYTES;   // 96 KB
    cudaFuncSetAttribute(gate_mma_kernel, cudaFuncAttributeMaxDynamicSharedMemorySize, smg);
    cudaFuncSetAttribute(mma_kernel<1, DIN, NH>,  cudaFuncAttributeMaxDynamicSharedMemorySize, smm);
    cudaFuncSetAttribute(mma_kernel<2, NH, NH>,   cudaFuncAttributeMaxDynamicSharedMemorySize, smm);
    cudaFuncSetAttribute(mma_kernel<3, NH, DOUT>, cudaFuncAttributeMaxDynamicSharedMemorySize, smm);

    // ---- fork ----
    cudaEventRecord(s_evF, 0);
    cudaStreamWaitEvent(s_side, s_evF, 0);

    // main: gate chain
    prep_gate_kernel<<<2688, 256>>>(x, gw, gob);                 // #1
    // side: expert prep + out clear
    cudaMemsetAsync(out, 0, (size_t)NTOK * DOUT * sizeof(float), s_side);
    prep_expert_kernel<<<8192, 256, 0, s_side>>>(w1, w2, w3);    // #2
    zero_cnt_kernel<<<1, 32>>>();                                // #3 (main)
    gate_mma_kernel<<<dim3(64, 2), 512, smg>>>(gb, gow);         // #4 -> ncu
    route_kernel<<<NTOK / 256, 256>>>();                         // #5

    // ---- join ----
    cudaEventRecord(s_evJ, s_side);
    cudaStreamWaitEvent(0, s_evJ, 0);

    mma_kernel<1, DIN, NH><<<dim3(64, NE, 2), 512, smm>>>(b1, nullptr);
    mma_kernel<2, NH, NH><<<dim3(64, NE, 2), 512, smm>>>(b2, nullptr);
    mma_kernel<3, NH, DOUT><<<dim3(64, NE, 1), 512, smm>>>(b3, out);
}

// round 14
// speedup vs baseline: 2.1972x; 1.2171x over previous
#include <cuda_runtime.h>
#include <cuda_bf16.h>
#include <cuda_fp16.h>
#include <cstdint>

#define NTOK 8192
#define DIN  256
#define DOUT 256
#define NE   16
#define NH   512

// ---------------------------------------------------------------------------
// Device scratch
// ---------------------------------------------------------------------------
__device__ int   g_cnt[NE];
__device__ int   g_tilecnt[64];
__device__ int   g_rtok[NE * NTOK];
__device__ float g_rgate[NE * NTOK];
__device__ float g_logits[NTOK * NE];

__device__ __half g_xh[NTOK * DIN], g_xlo[NTOK * DIN];
__device__ __half g_gwh[NH * DIN],  g_gwl[NH * DIN];    // gate_w planes [n=512][k=256]
__device__ __half g_w1T[NE * NH * DIN];     // [e][n=512][k=256]
__device__ __half g_w2T[NE * NH * NH];      // [e][512][512]
__device__ __half g_w3T[NE * DOUT * NH];    // [e][256][512]

// ---------------------------------------------------------------------------
// PTX helpers (compute_103-safe: cp.async + ldmatrix + mma.sync only)
// ---------------------------------------------------------------------------
__device__ __forceinline__ uint32_t smem_u32(const void* p) {
    uint32_t a;
    asm("{ .reg .u64 t; cvta.to.shared.u64 t, %1; cvt.u32.u64 %0, t; }" : "=r"(a) : "l"(p));
    return a;
}
#define CP16(dst, src) \
    asm volatile("cp.async.cg.shared.global [%0], [%1], 16;" :: "r"(dst), "l"(src) : "memory")
#define CP_COMMIT() asm volatile("cp.async.commit_group;" ::: "memory")
#define CP_WAIT(n)  asm volatile("cp.async.wait_group %0;" :: "n"(n) : "memory")

#define LDSM4(r, addr) \
    asm volatile("ldmatrix.sync.aligned.m8n8.x4.shared.b16 {%0,%1,%2,%3}, [%4];" \
        : "=r"((r)[0]), "=r"((r)[1]), "=r"((r)[2]), "=r"((r)[3]) : "r"(addr))

#define MMA16816H(c, a, b) \
    asm volatile("mma.sync.aligned.m16n8k16.row.col.f32.f16.f16.f32 " \
        "{%0,%1,%2,%3}, {%4,%5,%6,%7}, {%8,%9}, {%0,%1,%2,%3};" \
        : "+f"((c)[0]), "+f"((c)[1]), "+f"((c)[2]), "+f"((c)[3]) \
        : "r"((a)[0]), "r"((a)[1]), "r"((a)[2]), "r"((a)[3]), "r"((b)[0]), "r"((b)[1]))

// Pair-packed 64B-row swizzle: logical (row, k-unit) in 128B phys rows.
__device__ __forceinline__ uint32_t sw32(int row, int u) {
    return (uint32_t)((row >> 1) * 128 +
                      (((((row & 1) << 2) + u) ^ ((row >> 1) & 7)) << 4));
}

// ---------------------------------------------------------------------------
// prep_gate: x -> hi/lo fp16; gate_w -> transposed hi/lo; logits <- bias;
// zero g_cnt / g_tilecnt.
//   [0,2048) x split | [2048,2176) gw tiles | [2176,2688) logits | 2688 zero
// ---------------------------------------------------------------------------
__global__ __launch_bounds__(256) void prep_gate_kernel(
    const float* __restrict__ x, const float* __restrict__ gw,
    const float* __restrict__ gob)
{
    const int bid = blockIdx.x;
    const int tid = threadIdx.x;

    if (bid < 2048) {
        int base = bid * 512 + tid;
#pragma unroll
        for (int j = 0; j < 2; ++j) {
            int i = base + j * 256;
            float2 v = ((const float2*)x)[i];
            __half h0 = __float2half_rn(v.x), h1 = __float2half_rn(v.y);
            __half l0 = __float2half_rn(v.x - __half2float(h0));
            __half l1 = __float2half_rn(v.y - __half2float(h1));
            __half2 hh = __halves2half2(h0, h1), ll = __halves2half2(l0, l1);
            ((uint32_t*)g_xh)[i]  = *(uint32_t*)&hh;
            ((uint32_t*)g_xlo)[i] = *(uint32_t*)&ll;
        }
        return;
    }
    if (bid < 2176) {
        __shared__ float t[32][33];
        const int tx = tid & 31, ty = tid >> 5;
        int r = bid - 2048;
        int n0 = (r & 15) * 32, k0 = (r >> 4) * 32;
#pragma unroll
        for (int i = 0; i < 4; ++i)
            t[ty + 8 * i][tx] = gw[(long)(k0 + ty + 8 * i) * NH + n0 + tx];
        __syncthreads();
#pragma unroll
        for (int i = 0; i < 4; ++i) {
            float v = t[tx][ty + 8 * i];
            __half h = __float2half_rn(v);
            __half l = __float2half_rn(v - __half2float(h));
            size_t idx = (size_t)(n0 + ty + 8 * i) * DIN + k0 + tx;
            g_gwh[idx] = h;
            g_gwl[idx] = l;
        }
        return;
    }
    if (bid < 2688) {
        int i = (bid - 2176) * 256 + tid;
        g_logits[i] = gob[i & 15];
        return;
    }
    if (tid < NE) g_cnt[tid] = 0;
    if (tid < 64) g_tilecnt[tid] = 0;
}

// ---------------------------------------------------------------------------
// prep_expert: 3 weight transposes -> single fp16 planes.
// ---------------------------------------------------------------------------
__global__ __launch_bounds__(256) void prep_expert_kernel(
    const float* __restrict__ w1, const float* __restrict__ w2,
    const float* __restrict__ w3)
{
    const int bid = blockIdx.x;
    const int tid = threadIdx.x;
    __shared__ float t[32][33];
    const int tx = tid & 31, ty = tid >> 5;

    const float* src; long rs; int K, N, e, n0, k0;
    __half* dh;
    if (bid < 2048) {                    // w1
        int l = bid;
        e = l >> 7; int r = l & 127;
        n0 = (r & 15) * 32; k0 = (r >> 4) * 32;
        src = w1 + e * NH; rs = (long)NE * NH; K = DIN; N = NH;
        dh = g_w1T;
    } else if (bid < 6144) {             // w2
        int l = bid - 2048;
        e = l >> 8; int r = l & 255;
        n0 = (r & 15) * 32; k0 = (r >> 4) * 32;
        src = w2 + e * NH; rs = (long)NE * NH; K = NH; N = NH;
        dh = g_w2T;
    } else {                             // w3
        int l = bid - 6144;
        e = l >> 7; int r = l & 127;
        n0 = (r & 7) * 32; k0 = (r >> 3) * 32;
        src = w3 + e * DOUT; rs = (long)NE * DOUT; K = NH; N = DOUT;
        dh = g_w3T;
    }
    dh += (size_t)e * N * K;

#pragma unroll
    for (int i = 0; i < 4; ++i)
        t[ty + 8 * i][tx] = src[(long)(k0 + ty + 8 * i) * rs + n0 + tx];
    __syncthreads();
#pragma unroll
    for (int i = 0; i < 4; ++i)
        dh[(size_t)(n0 + ty + 8 * i) * K + k0 + tx] = __float2half_rn(t[tx][ty + 8 * i]);
}

// ---------------------------------------------------------------------------
// gate_mma: 3-product split-fp16 hidden GEMM + partial logits + (last CTA of
// each tile) routing. Grid (64, 2).
// ---------------------------------------------------------------------------
#define GSTG 49152
#define HSP  264
#define GPAD 20

__global__ __launch_bounds__(512, 1) void gate_mma_kernel(
    const float* __restrict__ gb, const float* __restrict__ gow)
{
    const int tile  = blockIdx.x;
    const int nbase = blockIdx.y * 256;

    extern __shared__ char smp[];
    const uint32_t smb = smem_u32(smp);
    __shared__ float sbias[256];
    __shared__ int   s_flag;

    const int tid  = threadIdx.x;
    const int wid  = tid >> 5, lane = tid & 31;
    const int wm   = wid & 3,  wn   = wid >> 2;

    if (tid < 256) sbias[tid] = gb[nbase + tid];
    __syncthreads();

    auto load_chunk = [&](int ch) {
        const int kbase = ch * 32;
        const uint32_t sb = smb + (ch & 3) * GSTG;
        {
            int row = tid >> 2, u = tid & 3;
            uint32_t d = sb + sw32(row, u);
            long arow = (long)tile * 128 + row;
            CP16(d,        g_xh  + arow * DIN + kbase + u * 8);
            CP16(d + 8192, g_xlo + arow * DIN + kbase + u * 8);
        }
#pragma unroll
        for (int i = 0; i < 2; ++i) {
            int idx = tid + i * 512;
            int row = idx >> 2, u = idx & 3;
            uint32_t d = sb + 16384 + sw32(row, u);
            CP16(d,         g_gwh + (size_t)(nbase + row) * DIN + kbase + u * 8);
            CP16(d + 16384, g_gwl + (size_t)(nbase + row) * DIN + kbase + u * 8);
        }
        CP_COMMIT();
    };

    float acc[2][8][4];
#pragma unroll
    for (int mf = 0; mf < 2; ++mf)
#pragma unroll
        for (int nf = 0; nf < 8; ++nf)
#pragma unroll
            for (int j = 0; j < 4; ++j) acc[mf][nf][j] = 0.f;

    load_chunk(0);
    load_chunk(1);
    load_chunk(2);

    const int NCH = DIN / 32;
    for (int ch = 0; ch < NCH; ++ch) {
        CP_WAIT(2);
        __syncthreads();
        if (ch + 3 < NCH) load_chunk(ch + 3);
        else              CP_COMMIT();

        const uint32_t sb  = smb + (ch & 3) * GSTG;
        const uint32_t aHI = sb, aLO = sb + 8192, bHI = sb + 16384, bLO = sb + 32768;

#pragma unroll
        for (int ks = 0; ks < 2; ++ks) {
            const int k0 = ks * 16;
            uint32_t ahi[2][4], alo[2][4];
            {
                int r_ = (lane & 7) + ((lane >> 3) & 1) * 8;
                int au = (k0 >> 3) + (lane >> 4);
#pragma unroll
                for (int mf = 0; mf < 2; ++mf) {
                    int r = wm * 32 + mf * 16 + r_;
                    LDSM4(ahi[mf], aHI + sw32(r, au));
                    LDSM4(alo[mf], aLO + sw32(r, au));
                }
            }
#pragma unroll
            for (int g = 0; g < 2; ++g) {
                uint32_t bhi[4][2], blo[4][2];
                int n_ = (lane & 7) + (lane >> 4) * 8;
                int bu = (k0 >> 3) + ((lane >> 3) & 1);
#pragma unroll
                for (int nb = 0; nb < 2; ++nb) {
                    int n = wn * 64 + (g * 2 + nb) * 16 + n_;
                    uint32_t r4[4];
                    LDSM4(r4, bHI + sw32(n, bu));
                    bhi[2 * nb][0] = r4[0]; bhi[2 * nb][1] = r4[1];
                    bhi[2 * nb + 1][0] = r4[2]; bhi[2 * nb + 1][1] = r4[3];
                    LDSM4(r4, bLO + sw32(n, bu));
                    blo[2 * nb][0] = r4[0]; blo[2 * nb][1] = r4[1];
                    blo[2 * nb + 1][0] = r4[2]; blo[2 * nb + 1][1] = r4[3];
                }
#pragma unroll
                for (int mf = 0; mf < 2; ++mf)
#pragma unroll
                    for (int nf = 0; nf < 4; ++nf)
                        MMA16816H(acc[mf][g * 4 + nf], ahi[mf], bhi[nf]);
#pragma unroll
                for (int mf = 0; mf < 2; ++mf)
#pragma unroll
                    for (int nf = 0; nf < 4; ++nf)
                        MMA16816H(acc[mf][g * 4 + nf], alo[mf], bhi[nf]);
#pragma unroll
                for (int mf = 0; mf < 2; ++mf)
#pragma unroll
                    for (int nf = 0; nf < 4; ++nf)
                        MMA16816H(acc[mf][g * 4 + nf], ahi[mf], blo[nf]);
            }
        }
    }
    __syncthreads();

    // ---- epilogue: partial logits ----
    float* Hsm  = (float*)smp;            // [64][HSP]
    float* gowS = Hsm + 64 * HSP;         // [256][GPAD]
    for (int idx = tid; idx < 256 * NE; idx += 512) {
        int r = idx >> 4, c = idx & 15;
        gowS[r * GPAD + c] = gow[(nbase + r) * NE + c];
    }

    const int grp = lane >> 2, t2 = (lane & 3) * 2;
#pragma unroll
    for (int hp = 0; hp < 2; ++hp) {
        if (hp == 1) __syncthreads();
        if ((wm >> 1) == hp) {
            int rbase = (wm & 1) * 32;
#pragma unroll
            for (int mf = 0; mf < 2; ++mf)
#pragma unroll
                for (int nf = 0; nf < 8; ++nf) {
                    const float* c = acc[mf][nf];
                    int col = wn * 64 + nf * 8 + t2;
#pragma unroll
                    for (int h8 = 0; h8 < 2; ++h8) {
                        int lr = rbase + mf * 16 + grp + h8 * 8;
                        Hsm[lr * HSP + col]     = fmaxf(c[h8 * 2] + sbias[col], 0.f);
                        Hsm[lr * HSP + col + 1] = fmaxf(c[h8 * 2 + 1] + sbias[col + 1], 0.f);
                    }
                }
        }
        __syncthreads();

        const int t = tid >> 3, s = tid & 7;
        float l[NE];
#pragma unroll
        for (int e = 0; e < NE; ++e) l[e] = 0.f;
#pragma unroll 4
        for (int i = 0; i < 32; ++i) {
            int rk = s + 8 * i;
            float v = Hsm[t * HSP + rk];
            const float4* gp = (const float4*)(gowS + rk * GPAD);
            float4 a = gp[0], b = gp[1], c4 = gp[2], d = gp[3];
            l[0]  = fmaf(v, a.x,  l[0]);   l[1]  = fmaf(v, a.y,  l[1]);
            l[2]  = fmaf(v, a.z,  l[2]);   l[3]  = fmaf(v, a.w,  l[3]);
            l[4]  = fmaf(v, b.x,  l[4]);   l[5]  = fmaf(v, b.y,  l[5]);
            l[6]  = fmaf(v, b.z,  l[6]);   l[7]  = fmaf(v, b.w,  l[7]);
            l[8]  = fmaf(v, c4.x, l[8]);   l[9]  = fmaf(v, c4.y, l[9]);
            l[10] = fmaf(v, c4.z, l[10]);  l[11] = fmaf(v, c4.w, l[11]);
            l[12] = fmaf(v, d.x,  l[12]);  l[13] = fmaf(v, d.y,  l[13]);
            l[14] = fmaf(v, d.z,  l[14]);  l[15] = fmaf(v, d.w,  l[15]);
        }
#pragma unroll
        for (int m2 = 1; m2 < 8; m2 <<= 1)
#pragma unroll
            for (int e = 0; e < NE; ++e)
                l[e] += __shfl_xor_sync(0xffffffffu, l[e], m2);

        int tok = tile * 128 + hp * 64 + t;
        atomicAdd(&g_logits[tok * NE + 2 * s],     l[2 * s]);
        atomicAdd(&g_logits[tok * NE + 2 * s + 1], l[2 * s + 1]);
    }

    // ---- routing: last CTA of this tile does top-2 + softmax + append ----
    __threadfence();
    __syncthreads();
    if (tid == 0) s_flag = atomicAdd(&g_tilecnt[tile], 1);
    __syncthreads();
    if (s_flag == 1 && tid < 128) {
        int tok = tile * 128 + tid;
        float v0 = -1e30f, v1 = -1e30f;
        int i0 = 0, i1 = 0;
#pragma unroll
        for (int e = 0; e < NE; ++e) {
            float lg = __ldcg(&g_logits[tok * NE + e]);
            if (lg > v0)      { v1 = v0; i1 = i0; v0 = lg; i0 = e; }
            else if (lg > v1) { v1 = lg; i1 = e; }
        }
        float e1 = __expf(v1 - v0);
        float sden = 1.f + e1;
        int p0 = atomicAdd(&g_cnt[i0], 1);
        g_rtok[i0 * NTOK + p0]  = tok;
        g_rgate[i0 * NTOK + p0] = 1.f / sden;
        int p1 = atomicAdd(&g_cnt[i1], 1);
        g_rtok[i1 * NTOK + p1]  = tok;
        g_rgate[i1 * NTOK + p1] = e1 / sden;
    }
}

// ---------------------------------------------------------------------------
// expert_fused: one CTA per (expert, 128-token tile) runs all 3 layers.
// smem: H1 [128KB: h1 chunks 0..15] | H2 [64KB: X tile, then h2 chunks 0..7]
//       | B stages [2 x 16KB].  h2 chunks 8..15 overwrite H1 chunks 0..7.
// Layout per chunk-block (8KB): element (row,k) at sw32(row,(k%32)/8)+(k%8)*2.
// ---------------------------------------------------------------------------
#define H1OFF 0
#define H2OFF 131072
#define BOFF  196608
#define EB    16384
#define SMEXP 229376

__global__ __launch_bounds__(512, 1) void expert_fused_kernel(
    const float* __restrict__ b1, const float* __restrict__ b2,
    const float* __restrict__ b3, float* __restrict__ outp)
{
    const int e    = blockIdx.y;
    const int tile = blockIdx.x;
    const int cnt  = g_cnt[e];
    if (tile * 128 >= cnt) return;
    const int m = min(128, cnt - tile * 128);

    extern __shared__ char smp[];
    const uint32_t smb = smem_u32(smp);
    __shared__ int   toks[128];
    __shared__ float gts[128];
    __shared__ float sbias[256];

    const int tid  = threadIdx.x;
    const int wid  = tid >> 5, lane = tid & 31;
    const int wm   = wid & 3,  wn   = wid >> 2;
    const int grp  = lane >> 2, t2 = (lane & 3) * 2;

    if (tid < 128) {
        int i = tile * 128 + tid;
        bool v = (i < cnt);
        toks[tid] = v ? g_rtok[e * NTOK + i] : 0;
        gts[tid]  = v ? g_rgate[e * NTOK + i] : 0.f;
    }
    __syncthreads();

    float acc[2][8][4];

    auto zero_acc = [&]() {
#pragma unroll
        for (int mf = 0; mf < 2; ++mf)
#pragma unroll
            for (int nf = 0; nf < 8; ++nf)
#pragma unroll
                for (int j = 0; j < 4; ++j) acc[mf][nf][j] = 0.f;
    };

    auto loadB = [&](const __half* Bp, int kstride, int ch) {
        const int kbase = ch * 32;
        const uint32_t sb = smb + BOFF + (ch & 1) * EB;
#pragma unroll
        for (int i = 0; i < 2; ++i) {
            int idx = tid + i * 512;
            int row = idx >> 2, u = idx & 3;
            CP16(sb + sw32(row, u), Bp + (size_t)row * kstride + kbase + u * 8);
        }
    };

    auto compute_chunk = [&](uint32_t aB, uint32_t bB) {
#pragma unroll
        for (int ks = 0; ks < 2; ++ks) {
            const int k0 = ks * 16;
            uint32_t af[2][4];
            {
                int r_ = (lane & 7) + ((lane >> 3) & 1) * 8;
                int au = (k0 >> 3) + (lane >> 4);
#pragma unroll
                for (int mf = 0; mf < 2; ++mf) {
                    int r = wm * 32 + mf * 16 + r_;
                    LDSM4(af[mf], aB + sw32(r, au));
                }
            }
#pragma unroll
            for (int g = 0; g < 2; ++g) {
                uint32_t bf[4][2];
                int n_ = (lane & 7) + (lane >> 4) * 8;
                int bu = (k0 >> 3) + ((lane >> 3) & 1);
#pragma unroll
                for (int nb = 0; nb < 2; ++nb) {
                    int n = wn * 64 + (g * 2 + nb) * 16 + n_;
                    uint32_t r4[4];
                    LDSM4(r4, bB + sw32(n, bu));
                    bf[2 * nb][0] = r4[0]; bf[2 * nb][1] = r4[1];
                    bf[2 * nb + 1][0] = r4[2]; bf[2 * nb + 1][1] = r4[3];
                }
#pragma unroll
                for (int mf = 0; mf < 2; ++mf)
#pragma unroll
                    for (int nf = 0; nf < 4; ++nf)
                        MMA16816H(acc[mf][g * 4 + nf], af[mf], bf[nf]);
            }
        }
    };

    // phase loop; abase maps chunk index -> smem A base address
    auto run_phase = [&](const __half* Bp, int kstride, int NCH, auto abase,
                         bool prologue) {
        if (prologue) {
            loadB(Bp, kstride, 0); CP_COMMIT();
            loadB(Bp, kstride, 1); CP_COMMIT();
        }
        for (int ch = 0; ch < NCH; ++ch) {
            CP_WAIT(1);
            __syncthreads();
            compute_chunk(abase(ch), smb + BOFF + (ch & 1) * EB);
            __syncthreads();
            if (ch + 2 < NCH) loadB(Bp, kstride, ch + 2);
            CP_COMMIT();
        }
    };

    // epilogue -> h chunks at smem byte base (chunk-local 0 of this half)
    auto epi_h = [&](uint32_t hbase) {
#pragma unroll
        for (int mf = 0; mf < 2; ++mf)
#pragma unroll
            for (int nf = 0; nf < 8; ++nf) {
                const float* c = acc[mf][nf];
                int col = wn * 64 + nf * 8 + t2;
                int chunk_local = wn * 2 + (nf >> 2);
                int u = nf & 3;
#pragma unroll
                for (int h8 = 0; h8 < 2; ++h8) {
                    int r = wm * 32 + mf * 16 + grp + h8 * 8;
                    __half2 h = __floats2half2_rn(
                        fmaxf(c[h8 * 2]     + sbias[col], 0.f),
                        fmaxf(c[h8 * 2 + 1] + sbias[col + 1], 0.f));
                    *(uint32_t*)(smp + hbase + chunk_local * 8192 +
                                 sw32(r, u) + t2 * 2) = *(uint32_t*)&h;
                }
            }
    };

    const __half* w1p = g_w1T + (size_t)e * NH * DIN;
    const __half* w2p = g_w2T + (size_t)e * NH * NH;
    const __half* w3p = g_w3T + (size_t)e * DOUT * NH;

    // ---- L1 (A = X in H2OFF; output h1 chunks) ----
    {
        // prologue: full X tile (8 chunks) + B chunk 0 in one group
#pragma unroll
        for (int c = 0; c < 8; ++c) {
            int row = tid >> 2, u = tid & 3;
            CP16(smb + H2OFF + c * 8192 + sw32(row, u),
                 g_xh + (size_t)toks[row] * DIN + c * 32 + u * 8);
        }
        loadB(w1p, DIN, 0); CP_COMMIT();
        loadB(w1p, DIN, 1); CP_COMMIT();

        auto abaseX = [&](int ch) { return smb + H2OFF + ch * 8192; };
#pragma unroll
        for (int half = 0; half < 2; ++half) {
            if (tid < 256) sbias[tid] = b1[e * NH + half * 256 + tid];
            zero_acc();
            run_phase(w1p + (size_t)half * 256 * DIN, DIN, DIN / 32, abaseX,
                      half == 1);
            epi_h(H1OFF + half * 65536);
            __syncthreads();
        }
    }

    // ---- L2 (A = h1 in H1OFF; output h2: half0 -> H2OFF, half1 -> H1OFF) ----
    {
        auto abaseH1 = [&](int ch) { return smb + H1OFF + ch * 8192; };
#pragma unroll
        for (int half = 0; half < 2; ++half) {
            if (tid < 256) sbias[tid] = b2[e * NH + half * 256 + tid];
            zero_acc();
            run_phase(w2p + (size_t)half * 256 * NH, NH, NH / 32, abaseH1, true);
            epi_h(half == 0 ? H2OFF : H1OFF);
            __syncthreads();
        }
    }

    // ---- L3 (A = h2 split across H2OFF/H1OFF; gated scatter to out) ----
    {
        if (tid < 256) sbias[tid] = b3[e * DOUT + tid];
        zero_acc();
        auto abaseH2 = [&](int ch) {
            return (ch < 8) ? (smb + H2OFF + ch * 8192)
                            : (smb + H1OFF + (ch - 8) * 8192);
        };
        run_phase(w3p, NH, NH / 32, abaseH2, true);

#pragma unroll
        for (int mf = 0; mf < 2; ++mf)
#pragma unroll
            for (int nf = 0; nf < 8; ++nf) {
                const float* c = acc[mf][nf];
                const int col = wn * 64 + nf * 8 + t2;
#pragma unroll
                for (int h8 = 0; h8 < 2; ++h8) {
                    const int r = wm * 32 + mf * 16 + grp + h8 * 8;
                    if (r < m) {
                        float g = gts[r];
                        float* orow = outp + (size_t)toks[r] * DOUT + col;
                        atomicAdd(orow,     g * (c[h8 * 2]     + sbias[col]));
                        atomicAdd(orow + 1, g * (c[h8 * 2 + 1] + sbias[col + 1]));
                    }
                }
            }
    }
}

// ---------------------------------------------------------------------------
extern "C" void kernel_launch(void* const* d_in, const int* in_sizes, int n_in,
                              void* d_out, int out_size)
{
    const float* x   = (const float*)d_in[0];
    const float* gw  = (const float*)d_in[1];
    const float* gb  = (const float*)d_in[2];
    const float* gow = (const float*)d_in[3];
    const float* gob = (const float*)d_in[4];
    const float* w1  = (const float*)d_in[5];
    const float* b1  = (const float*)d_in[6];
    const float* w2  = (const float*)d_in[7];
    const float* b2  = (const float*)d_in[8];
    const float* w3  = (const float*)d_in[9];
    const float* b3  = (const float*)d_in[10];
    float* out = (float*)d_out;

    static cudaStream_t s_side = nullptr;
    static cudaEvent_t  s_evF = nullptr, s_evJ = nullptr;
    if (!s_side) {
        cudaStreamCreateWithFlags(&s_side, cudaStreamNonBlocking);
        cudaEventCreateWithFlags(&s_evF, cudaEventDisableTiming);
        cudaEventCreateWithFlags(&s_evJ, cudaEventDisableTiming);
    }

    const int smg = 4 * GSTG;    // 192 KB
    cudaFuncSetAttribute(gate_mma_kernel, cudaFuncAttributeMaxDynamicSharedMemorySize, smg);
    cudaFuncSetAttribute(expert_fused_kernel, cudaFuncAttributeMaxDynamicSharedMemorySize, SMEXP);

    // ---- fork ----
    cudaEventRecord(s_evF, 0);
    cudaStreamWaitEvent(s_side, s_evF, 0);

    prep_gate_kernel<<<2689, 256>>>(x, gw, gob);                 // #1 (main)
    cudaMemsetAsync(out, 0, (size_t)NTOK * DOUT * sizeof(float), s_side);
    prep_expert_kernel<<<8192, 256, 0, s_side>>>(w1, w2, w3);    // #2 (side)
    gate_mma_kernel<<<dim3(64, 2), 512, smg>>>(gb, gow);         // #3 (main)

    // ---- join ----
    cudaEventRecord(s_evJ, s_side);
    cudaStreamWaitEvent(0, s_evJ, 0);

    expert_fused_kernel<<<dim3(64, NE), 512, SMEXP>>>(b1, b2, b3, out);  // #4 -> ncu
}